// round 10
// baseline (speedup 1.0000x reference)
#include <cuda_runtime.h>
#include <cuda_bf16.h>
#include <cstdint>

#define NPTS   8192
#define CH     32
#define TILE   256
#define MT     32                      // NPTS / TILE
#define NTILES 528                     // MT*(MT+1)/2 upper-triangle tile pairs
#define NPREP  128                     // prep blocks (8192 / 64)
#define PQ     12                      // padded row stride in b32 words (48B; 32B used)

// ---------------- device scratch (no allocations allowed) -------------------
__device__ float    g_sq[NPTS];           // full 32-ch tree norms (exact path)
__device__ float    g_sq16[NPTS];         // first-16-ch norms (screen only)
__device__ uint32_t g_xbf[NPTS * 8];      // [n][8] bf16x2 words: channels 0..15
__device__ float    g_partial[NTILES];
__device__ float    g_diagpart[NPREP];
__device__ int      g_counter;            // zero-init; reset by last CTA

// ---------------------------------------------------------------------------
// Kernel A (prep): per-point full tree-sq + sequential-FMA self-dot -> exact
// diagonal loss (bit-identical arithmetic to the passing R2..R9 pipeline),
// 16-ch screen norm, and bf16 pack of channels 0..15 (staged via smem).
// ---------------------------------------------------------------------------
__global__ __launch_bounds__(64) void prep_kernel(const float* __restrict__ x) {
    __shared__ uint32_t s8[64 * 8];
    __shared__ float    red[64];

    int tid = threadIdx.x;
    int n = blockIdx.x * 64 + tid;

    float v[CH];
#pragma unroll
    for (int c = 0; c < CH; ++c) v[c] = x[c * NPTS + n];

    // full sq: non-FMA products, 4-accumulator tree (XLA-reduce flavor)
    float a0 = 0.f, a1 = 0.f, a2 = 0.f, a3 = 0.f;
#pragma unroll
    for (int c = 0; c < CH; c += 4) {
        a0 = __fadd_rn(a0, __fmul_rn(v[c + 0], v[c + 0]));
        a1 = __fadd_rn(a1, __fmul_rn(v[c + 1], v[c + 1]));
        a2 = __fadd_rn(a2, __fmul_rn(v[c + 2], v[c + 2]));
        a3 = __fadd_rn(a3, __fmul_rn(v[c + 3], v[c + 3]));
    }
    float sq = __fadd_rn(__fadd_rn(a0, a1), __fadd_rn(a2, a3));
    g_sq[n] = sq;

    // self-dot: sequential FMA chain (GEMM flavor) -> diagonal noise d2 ~ +-eps
    float dot = 0.f;
#pragma unroll
    for (int c = 0; c < CH; ++c) dot = fmaf(v[c], v[c], dot);

    float d2 = fmaf(-2.f, dot, __fadd_rn(sq, sq));
    float f = 0.f;
    if (d2 < 4.f) {
        d2 = fmaxf(d2, 0.f);
        float d = sqrtf(d2);
        f = fmaf(1.5f, d, fmaf(-0.5f, d2, -1.f));
    }

    // 16-ch screen norm
    float s16 = 0.f;
#pragma unroll
    for (int c = 0; c < 16; ++c) s16 = fmaf(v[c], v[c], s16);
    g_sq16[n] = s16;

    // bf16 pack of channels 0..15 -> 8 words, staged for coalesced store
#pragma unroll
    for (int w = 0; w < 8; ++w) {
        __nv_bfloat162 pk = __floats2bfloat162_rn(v[2 * w], v[2 * w + 1]);
        s8[tid * 8 + w] = *reinterpret_cast<uint32_t*>(&pk);
    }
    __syncthreads();
    uint32_t* dst = &g_xbf[blockIdx.x * 64 * 8];
#pragma unroll
    for (int i = tid; i < 512; i += 64) dst[i] = s8[i];

    // deterministic block reduction of diagonal contributions
    red[tid] = f;
    __syncthreads();
#pragma unroll
    for (int s = 32; s > 0; s >>= 1) {
        if (tid < s) red[tid] += red[tid + s];
        __syncthreads();
    }
    if (tid == 0) g_diagpart[blockIdx.x] = red[0];
}

// ---------------------------------------------------------------------------
// mma.sync m16n8k16 bf16 (sm_80+ baseline PTX; portable to plain sm_103).
// ---------------------------------------------------------------------------
__device__ __forceinline__ void hmma16816(float* c, const uint32_t* a, const uint32_t* b) {
    asm volatile(
        "mma.sync.aligned.m16n8k16.row.col.f32.bf16.bf16.f32 "
        "{%0,%1,%2,%3}, {%4,%5,%6,%7}, {%8,%9}, {%0,%1,%2,%3};"
        : "+f"(c[0]), "+f"(c[1]), "+f"(c[2]), "+f"(c[3])
        : "r"(a[0]), "r"(a[1]), "r"(a[2]), "r"(a[3]), "r"(b[0]), "r"(b[1]));
}

// ---------------------------------------------------------------------------
// Exact fp32 recompute of one pair (full 32 channels, reference formula).
// Only ever emitted inside recover_nj (cold, out-of-line).
// ---------------------------------------------------------------------------
__device__ float exact_pair(const float* __restrict__ x, int gi, int gj) {
    float dt = 0.f;
#pragma unroll
    for (int c = 0; c < CH; ++c)
        dt = fmaf(x[c * NPTS + gi], x[c * NPTS + gj], dt);
    float e2 = fmaf(-2.f, dt, g_sq[gi] + g_sq[gj]);
    if (e2 < 4.f) {
        e2 = fmaxf(e2, 0.f);
        float d = sqrtf(e2);
        return fmaf(1.5f, d, fmaf(-0.5f, e2, -1.f));
    }
    return 0.f;
}

// ---------------------------------------------------------------------------
// Cold recovery for one flagged nj: re-screen this lane's 16 pairs with a
// scalar bf16 dot from smem (same data as the MMA, so same soundness margin),
// and exactly recompute (fp32, 32 ch) each individually-flagged pair.
// __noinline__: exactly ONE call site -> tiny hot loop, all cold code here.
// ---------------------------------------------------------------------------
__device__ __noinline__ float recover_nj(const float* __restrict__ x,
                                         const uint32_t* As_p, const uint32_t* Bs_p,
                                         const float* s16A_p, const float* s16B_p,
                                         int I, int J, int m0, int qr, int colb) {
    float acc = 0.f;
#pragma unroll 1
    for (int mi = 0; mi < 4; ++mi) {
#pragma unroll 1
        for (int rh = 0; rh < 2; ++rh) {
            int r = m0 + mi * 16 + qr + rh * 8;
            float si = s16A_p[r];
#pragma unroll 1
            for (int cb = 0; cb < 2; ++cb) {
                int col = colb + cb;
                float dot = 0.f;
#pragma unroll
                for (int w = 0; w < 8; ++w) {
                    __nv_bfloat162 av, bv;
                    uint32_t aw = As_p[r * PQ + w];
                    uint32_t bw = Bs_p[col * PQ + w];
                    av = *reinterpret_cast<__nv_bfloat162*>(&aw);
                    bv = *reinterpret_cast<__nv_bfloat162*>(&bw);
                    float2 af = __bfloat1622float2(av);
                    float2 bf = __bfloat1622float2(bv);
                    dot = fmaf(af.x, bf.x, dot);
                    dot = fmaf(af.y, bf.y, dot);
                }
                float d2s = fmaf(-2.f, dot, si + s16B_p[col]);
                int gi = I * TILE + r;
                int gj = J * TILE + col;
                if (d2s < 6.f && gi != gj)
                    acc += exact_pair(x, gi, gj);
            }
        }
    }
    return acc;
}

// ---------------------------------------------------------------------------
// Kernel B (tile): one CTA per (I,J) 256x256 tile pair, J >= I, 8 warps.
// K=16 bf16 HMMA screen. Hot loop is BRANCH-FREE: per nj it does 2 LDS,
// 4 independent MMAs, a screen pass, and sets one bit of a per-lane mask.
// All recovery is out-of-line in recover_nj (single call site after loop).
// Diagonal tiles take the same path: their near-diagonal elements flag
// their nj and recovery handles them (gi==gj skipped; diag loss in prep).
// Last CTA performs the deterministic final reduction.
// ---------------------------------------------------------------------------
__global__ __launch_bounds__(256, 4) void tile_kernel(const float* __restrict__ x,
                                                      float* __restrict__ out) {
    __shared__ __align__(16) uint32_t As[TILE * PQ];   // 12 KB
    __shared__ __align__(16) uint32_t Bs[TILE * PQ];   // 12 KB
    __shared__ float s16A[TILE];
    __shared__ float s16B[TILE];
    __shared__ float red[256];
    __shared__ bool  amlast;

    int tid = threadIdx.x;
    int wid = tid >> 5;
    int lane = tid & 31;

    // decode blockIdx -> (I, J) over upper triangle
    int bid = blockIdx.x;
    int I = 0, rem = bid;
    while (rem >= MT - I) { rem -= MT - I; ++I; }
    int J = I + rem;
    bool diag = (I == J);

    // fill tiles: thread t owns row t of A (and of B when off-diagonal)
    {
        int gA = I * TILE + tid;
        const uint4* srcA = reinterpret_cast<const uint4*>(&g_xbf[gA * 8]);
        uint4* dA = reinterpret_cast<uint4*>(As + tid * PQ);
        dA[0] = srcA[0];
        dA[1] = srcA[1];
        s16A[tid] = g_sq16[gA];
        if (!diag) {
            int gB = J * TILE + tid;
            const uint4* srcB = reinterpret_cast<const uint4*>(&g_xbf[gB * 8]);
            uint4* dB = reinterpret_cast<uint4*>(Bs + tid * PQ);
            dB[0] = srcB[0];
            dB[1] = srcB[1];
            s16B[tid] = g_sq16[gB];
        }
    }
    __syncthreads();

    const uint32_t* Bsrc = diag ? As : Bs;
    const float*    sjv  = diag ? s16A : s16B;

    int m0 = (wid & 3) * 64;     // row block of this warp (64 rows)
    int n0 = (wid >> 2) * 128;   // col block of this warp (128 cols)
    int qr = lane >> 2;          // 0..7
    int qc = lane & 3;           // 0..3

    // A fragments (K=16: one fragment per 16-row slab) + lane row norms
    uint32_t afr[4][4];
    float siv[4][2];
#pragma unroll
    for (int mi = 0; mi < 4; ++mi) {
        int r0 = m0 + mi * 16 + qr;
        int r1 = r0 + 8;
        afr[mi][0] = As[r0 * PQ + qc];
        afr[mi][1] = As[r1 * PQ + qc];
        afr[mi][2] = As[r0 * PQ + qc + 4];
        afr[mi][3] = As[r1 * PQ + qc + 4];
        siv[mi][0] = s16A[r0];
        siv[mi][1] = s16A[r1];
    }

    unsigned mask = 0;   // bit nj set -> this lane needs recovery for nj

#pragma unroll
    for (int nj = 0; nj < 16; ++nj) {
        int jrow = n0 + nj * 8 + qr;
        uint32_t b[2];
        b[0] = Bsrc[jrow * PQ + qc];
        b[1] = Bsrc[jrow * PQ + qc + 4];

        float acc[4][4];
#pragma unroll
        for (int mi = 0; mi < 4; ++mi) {
            acc[mi][0] = acc[mi][1] = acc[mi][2] = acc[mi][3] = 0.f;
            hmma16816(acc[mi], afr[mi], b);
        }

        int colb = n0 + nj * 8 + 2 * qc;
        float sj0 = sjv[colb];
        float sj1 = sjv[colb + 1];

        float mn = 1e30f;
#pragma unroll
        for (int mi = 0; mi < 4; ++mi) {
            float d0 = fmaf(-2.f, acc[mi][0], siv[mi][0] + sj0);
            float d1 = fmaf(-2.f, acc[mi][1], siv[mi][0] + sj1);
            float d2 = fmaf(-2.f, acc[mi][2], siv[mi][1] + sj0);
            float d3 = fmaf(-2.f, acc[mi][3], siv[mi][1] + sj1);
            mn = fminf(mn, fminf(fminf(d0, d1), fminf(d2, d3)));
        }
        mask |= ((unsigned)(mn < 6.f)) << nj;   // branch-free flag
    }

    // cold recovery: pop flagged njs (expected ~0-2 off-diagonal, ~8 on diag)
    float local = 0.f;
    while (mask) {
        int nj = __ffs(mask) - 1;
        mask &= mask - 1;
        int colb = n0 + nj * 8 + 2 * qc;
        local += recover_nj(x, As, Bsrc, s16A, sjv, I, J, m0, qr, colb);
    }

    if (!diag) local *= 2.f;   // symmetry: (I,J) and (J,I) identical

    // deterministic block reduction
    red[tid] = local;
    __syncthreads();
#pragma unroll
    for (int s = 128; s > 0; s >>= 1) {
        if (tid < s) red[tid] += red[tid + s];
        __syncthreads();
    }
    if (tid == 0) g_partial[bid] = red[0];

    // last CTA performs the deterministic final reduction
    if (tid == 0) {
        __threadfence();
        int prev = atomicAdd(&g_counter, 1);
        amlast = (prev == NTILES - 1);
    }
    __syncthreads();
    if (amlast) {
        float s = 0.f;
        for (int i = tid; i < NTILES; i += 256) s += g_partial[i];
        for (int i = tid; i < NPREP; i += 256) s += g_diagpart[i];
        red[tid] = s;
        __syncthreads();
#pragma unroll
        for (int k = 128; k > 0; k >>= 1) {
            if (tid < k) red[tid] += red[tid + k];
            __syncthreads();
        }
        if (tid == 0) {
            out[0] = 0.25f * red[0];
            g_counter = 0;           // reset for next graph replay
        }
    }
}

// ---------------------------------------------------------------------------
extern "C" void kernel_launch(void* const* d_in, const int* in_sizes, int n_in,
                              void* d_out, int out_size) {
    const float* x = (const float*)d_in[0];   // [1, 32, 8192] fp32, channel-major
    float* out = (float*)d_out;

    prep_kernel<<<NPREP, 64>>>(x);
    tile_kernel<<<NTILES, 256>>>(x, out);
}

// round 11
// speedup vs baseline: 1.8903x; 1.8903x over previous
#include <cuda_runtime.h>
#include <cuda_bf16.h>
#include <cstdint>

#define NPTS   8192
#define CH     32
#define TILE   256
#define MT     32                      // NPTS / TILE
#define NTILES 528                     // MT*(MT+1)/2 upper-triangle tile pairs
#define NPREP  128                     // prep blocks (8192 / 64)
#define LDPW   20                      // padded row stride in b32 words (80 bytes)

// ---------------- device scratch (no allocations allowed) -------------------
__device__ float    g_sq[NPTS];
__device__ uint32_t g_xbf[NPTS * 16];     // [n][16] bf16x2: point-major rows, 32 channels
__device__ float    g_partial[NTILES];
__device__ float    g_diagpart[NPREP];
__device__ int      g_counter;            // zero-init; reset by last CTA

// ---------------------------------------------------------------------------
// Kernel A (prep): per-point sq (non-FMA tree) + sequential-FMA self-dot ->
// diagonal loss with the reference's rounding-noise structure (bit-identical
// per-point arithmetic to every passing round), plus fp32 -> bf16 pack of all
// 32 channels, staged via smem for coalesced stores. 128 CTAs x 64 threads
// (the fastest measured prep configuration).
// ---------------------------------------------------------------------------
__global__ __launch_bounds__(64) void prep_kernel(const float* __restrict__ x) {
    __shared__ uint32_t st[64 * 16];    // staged bf16 rows (4 KB)
    __shared__ float    red[64];

    int tid = threadIdx.x;
    int n = blockIdx.x * 64 + tid;

    float v[CH];
#pragma unroll
    for (int c = 0; c < CH; ++c) v[c] = x[c * NPTS + n];

    // sq: non-FMA rounded products, 4-accumulator tree (XLA-reduce flavor)
    float a0 = 0.f, a1 = 0.f, a2 = 0.f, a3 = 0.f;
#pragma unroll
    for (int c = 0; c < CH; c += 4) {
        a0 = __fadd_rn(a0, __fmul_rn(v[c + 0], v[c + 0]));
        a1 = __fadd_rn(a1, __fmul_rn(v[c + 1], v[c + 1]));
        a2 = __fadd_rn(a2, __fmul_rn(v[c + 2], v[c + 2]));
        a3 = __fadd_rn(a3, __fmul_rn(v[c + 3], v[c + 3]));
    }
    float sq = __fadd_rn(__fadd_rn(a0, a1), __fadd_rn(a2, a3));
    g_sq[n] = sq;

    // self-dot: sequential FMA chain (GEMM flavor) -> diagonal noise d2 ~ +-eps
    float dot = 0.f;
#pragma unroll
    for (int c = 0; c < CH; ++c) dot = fmaf(v[c], v[c], dot);

    float d2 = fmaf(-2.f, dot, __fadd_rn(sq, sq));
    float f = 0.f;
    if (d2 < 4.f) {
        d2 = fmaxf(d2, 0.f);
        float d = sqrtf(d2);
        f = fmaf(1.5f, d, fmaf(-0.5f, d2, -1.f));
    }

    // bf16 pack: 16 bf16x2 words per point, staged for coalesced store
#pragma unroll
    for (int c2 = 0; c2 < 16; ++c2) {
        __nv_bfloat162 pk = __floats2bfloat162_rn(v[2 * c2], v[2 * c2 + 1]);
        st[tid * 16 + c2] = *reinterpret_cast<uint32_t*>(&pk);
    }
    __syncthreads();
    uint32_t* dst = &g_xbf[blockIdx.x * 64 * 16];
#pragma unroll
    for (int i = tid; i < 1024; i += 64) dst[i] = st[i];

    // deterministic block reduction of diagonal contributions
    red[tid] = f;
    __syncthreads();
#pragma unroll
    for (int s = 32; s > 0; s >>= 1) {
        if (tid < s) red[tid] += red[tid + s];
        __syncthreads();
    }
    if (tid == 0) g_diagpart[blockIdx.x] = red[0];
}

// ---------------------------------------------------------------------------
// mma.sync m16n8k16 bf16 (sm_80+ baseline PTX; portable to plain sm_103).
// ---------------------------------------------------------------------------
__device__ __forceinline__ void hmma16816(float* c, const uint32_t* a, const uint32_t* b) {
    asm volatile(
        "mma.sync.aligned.m16n8k16.row.col.f32.bf16.bf16.f32 "
        "{%0,%1,%2,%3}, {%4,%5,%6,%7}, {%8,%9}, {%0,%1,%2,%3};"
        : "+f"(c[0]), "+f"(c[1]), "+f"(c[2]), "+f"(c[3])
        : "r"(a[0]), "r"(a[1]), "r"(a[2]), "r"(a[3]), "r"(b[0]), "r"(b[1]));
}

// ---------------------------------------------------------------------------
// Cold path: lane-exact fp32 recompute of this lane's 8 rows x 32 cols.
// Runs only when the bf16 screen flags (probability ~1e-9 per lane).
// ---------------------------------------------------------------------------
__device__ __noinline__ float slow_lane(const float* __restrict__ x,
                                        int I, int J, int m0, int n0,
                                        int qr, int qc) {
    float acc = 0.f;
#pragma unroll 1
    for (int r = 0; r < 8; ++r) {
        int gi = I * TILE + m0 + (r >> 1) * 16 + qr + (r & 1) * 8;
        float si = g_sq[gi];
#pragma unroll 1
        for (int cidx = 0; cidx < 32; ++cidx) {
            int gj = J * TILE + n0 + (cidx >> 1) * 8 + 2 * qc + (cidx & 1);
            if (gi == gj) continue;
            float dt = 0.f;
#pragma unroll
            for (int c = 0; c < CH; ++c)
                dt = fmaf(x[c * NPTS + gi], x[c * NPTS + gj], dt);
            float e2 = fmaf(-2.f, dt, si + g_sq[gj]);
            if (e2 < 4.f) {
                e2 = fmaxf(e2, 0.f);
                float d = sqrtf(e2);
                acc += fmaf(1.5f, d, fmaf(-0.5f, e2, -1.f));
            }
        }
    }
    return acc;
}

// ---------------------------------------------------------------------------
// Kernel B (tile): EXACT R5 structure (best measured): one CTA per (I,J)
// 256x256 tile pair, J >= I, 8 warps; K=32 bf16 HMMA in 8-MMA bursts per nj;
// branch-free fmin screen off-diagonal with a single cold call; branchy
// exact path on diagonal tiles. No min-blocks register cap.
// Last CTA performs the deterministic final reduction (replaces kernel C).
// ---------------------------------------------------------------------------
__global__ __launch_bounds__(256) void tile_kernel(const float* __restrict__ x,
                                                   float* __restrict__ out) {
    __shared__ __align__(16) uint32_t As[TILE * LDPW];   // 20 KB
    __shared__ __align__(16) uint32_t Bs[TILE * LDPW];   // 20 KB
    __shared__ float sqA[TILE];
    __shared__ float sqB[TILE];
    __shared__ float red[256];
    __shared__ bool  amlast;

    int tid = threadIdx.x;
    int wid = tid >> 5;
    int lane = tid & 31;

    // decode blockIdx -> (I, J) over upper triangle
    int bid = blockIdx.x;
    int I = 0, rem = bid;
    while (rem >= MT - I) { rem -= MT - I; ++I; }
    int J = I + rem;

    // fill A/B tiles: 256 threads, 2 tiles x 256 rows -> 2 rows per thread
    {
        int which = tid >> 7;                  // 0 -> A, 1 -> B
        int r0 = tid & 127;
#pragma unroll
        for (int rr = 0; rr < 2; ++rr) {
            int row  = r0 + rr * 128;
            int base = (which ? J : I) * TILE + row;
            const uint4* src = reinterpret_cast<const uint4*>(&g_xbf[base * 16]);
            uint4* dst = reinterpret_cast<uint4*>((which ? Bs : As) + row * LDPW);
#pragma unroll
            for (int q = 0; q < 4; ++q) dst[q] = src[q];
            if (which) sqB[row] = g_sq[base];
            else       sqA[row] = g_sq[base];
        }
    }
    __syncthreads();

    int m0 = (wid & 3) * 64;     // row block of this warp (64 rows)
    int n0 = (wid >> 2) * 128;   // col block of this warp (128 cols)
    int qr = lane >> 2;          // 0..7
    int qc = lane & 3;           // 0..3

    // A fragments: afr[mi][kf][4], mi = 0..3 (16-row slabs)
    uint32_t afr[4][2][4];
#pragma unroll
    for (int mi = 0; mi < 4; ++mi) {
        int r0 = m0 + mi * 16 + qr;
        int r1 = r0 + 8;
#pragma unroll
        for (int kf = 0; kf < 2; ++kf) {
            int kw = kf * 8 + qc;
            afr[mi][kf][0] = As[r0 * LDPW + kw];
            afr[mi][kf][1] = As[r1 * LDPW + kw];
            afr[mi][kf][2] = As[r0 * LDPW + kw + 4];
            afr[mi][kf][3] = As[r1 * LDPW + kw + 4];
        }
    }

    float siv[4][2];
#pragma unroll
    for (int mi = 0; mi < 4; ++mi) {
        siv[mi][0] = sqA[m0 + mi * 16 + qr];
        siv[mi][1] = sqA[m0 + mi * 16 + qr + 8];
    }

    float local = 0.f;

    if (I != J) {
        // ---- hot path: branch-free screen over 16 n-fragments ----
        float dmin = 1e30f;
#pragma unroll
        for (int nj = 0; nj < 16; ++nj) {
            int jrow = n0 + nj * 8 + qr;
            uint32_t bfr[2][2];
#pragma unroll
            for (int kf = 0; kf < 2; ++kf) {
                int kw = kf * 8 + qc;
                bfr[kf][0] = Bs[jrow * LDPW + kw];
                bfr[kf][1] = Bs[jrow * LDPW + kw + 4];
            }
            float acc[4][4];
#pragma unroll
            for (int mi = 0; mi < 4; ++mi) {
                acc[mi][0] = acc[mi][1] = acc[mi][2] = acc[mi][3] = 0.f;
                hmma16816(acc[mi], afr[mi][0], bfr[0]);
                hmma16816(acc[mi], afr[mi][1], bfr[1]);
            }
            int colb = n0 + nj * 8 + 2 * qc;
            float sj0 = sqB[colb];
            float sj1 = sqB[colb + 1];
#pragma unroll
            for (int mi = 0; mi < 4; ++mi) {
#pragma unroll
                for (int e = 0; e < 4; ++e) {
                    float s = siv[mi][e >> 1] + ((e & 1) ? sj1 : sj0);
                    dmin = fminf(dmin, fmaf(-2.f, acc[mi][e], s));
                }
            }
        }
        float contrib = 0.f;
        if (dmin < 8.f)   // conservative screen (true cut 4, bf16 err << 4)
            contrib = slow_lane(x, I, J, m0, n0, qr, qc);
        local = 2.f * contrib;   // symmetry: (I,J) and (J,I) identical
    } else {
        // ---- diagonal tile: per-element exact path on flag ----
#pragma unroll
        for (int nj = 0; nj < 16; ++nj) {
            int jrow = n0 + nj * 8 + qr;
            uint32_t bfr[2][2];
#pragma unroll
            for (int kf = 0; kf < 2; ++kf) {
                int kw = kf * 8 + qc;
                bfr[kf][0] = As[jrow * LDPW + kw];
                bfr[kf][1] = As[jrow * LDPW + kw + 4];
            }
            float acc[4][4];
#pragma unroll
            for (int mi = 0; mi < 4; ++mi) {
                acc[mi][0] = acc[mi][1] = acc[mi][2] = acc[mi][3] = 0.f;
                hmma16816(acc[mi], afr[mi][0], bfr[0]);
                hmma16816(acc[mi], afr[mi][1], bfr[1]);
            }
            int colb = n0 + nj * 8 + 2 * qc;
            float sj0 = sqA[colb];
            float sj1 = sqA[colb + 1];
            int   gj0 = J * TILE + colb;
#pragma unroll
            for (int mi = 0; mi < 4; ++mi) {
#pragma unroll
                for (int e = 0; e < 4; ++e) {
                    int   rh = e >> 1;
                    float sj = (e & 1) ? sj1 : sj0;
                    int   gj = gj0 + (e & 1);
                    float si = siv[mi][rh];
                    float d2s = fmaf(-2.f, acc[mi][e], si + sj);
                    if (d2s < 8.f) {
                        int gi = I * TILE + m0 + mi * 16 + qr + rh * 8;
                        if (gi != gj) {
                            float dt = 0.f;
#pragma unroll
                            for (int c = 0; c < CH; ++c)
                                dt = fmaf(x[c * NPTS + gi], x[c * NPTS + gj], dt);
                            float e2 = fmaf(-2.f, dt, si + sj);
                            if (e2 < 4.f) {
                                e2 = fmaxf(e2, 0.f);
                                float d = sqrtf(e2);
                                local += fmaf(1.5f, d, fmaf(-0.5f, e2, -1.f));
                            }
                        }
                    }
                }
            }
        }
    }

    // deterministic block reduction
    red[tid] = local;
    __syncthreads();
#pragma unroll
    for (int s = 128; s > 0; s >>= 1) {
        if (tid < s) red[tid] += red[tid + s];
        __syncthreads();
    }
    if (tid == 0) g_partial[bid] = red[0];

    // last CTA performs the deterministic final reduction
    if (tid == 0) {
        __threadfence();
        int prev = atomicAdd(&g_counter, 1);
        amlast = (prev == NTILES - 1);
    }
    __syncthreads();
    if (amlast) {
        float s = 0.f;
        for (int i = tid; i < NTILES; i += 256) s += g_partial[i];
        for (int i = tid; i < NPREP; i += 256) s += g_diagpart[i];
        red[tid] = s;
        __syncthreads();
#pragma unroll
        for (int k = 128; k > 0; k >>= 1) {
            if (tid < k) red[tid] += red[tid + k];
            __syncthreads();
        }
        if (tid == 0) {
            out[0] = 0.25f * red[0];
            g_counter = 0;           // reset for next graph replay
        }
    }
}

// ---------------------------------------------------------------------------
extern "C" void kernel_launch(void* const* d_in, const int* in_sizes, int n_in,
                              void* d_out, int out_size) {
    const float* x = (const float*)d_in[0];   // [1, 32, 8192] fp32, channel-major
    float* out = (float*)d_out;

    prep_kernel<<<NPREP, 64>>>(x);
    tile_kernel<<<NTILES, 256>>>(x, out);
}

// round 12
// speedup vs baseline: 2.5479x; 1.3479x over previous
#include <cuda_runtime.h>
#include <cuda_bf16.h>
#include <cstdint>

#define NPTS   8192
#define CH     32
#define TILE   256
#define MT     32                      // NPTS / TILE
#define NTILES 528                     // MT*(MT+1)/2 upper-triangle tile pairs
#define NPREP  128                     // prep blocks (8192 / 64)
#define LDPW   20                      // padded row stride in b32 words (80 bytes)

// ---------------- device scratch (no allocations allowed) -------------------
__device__ float    g_sq[NPTS];           // full 32-ch tree norms (exact path)
__device__ uint32_t g_xa[NPTS * 16];      // A-flavor rows: ch0..27, (-s28/2, 1), (0,0)
__device__ uint32_t g_xb[NPTS * 16];      // B-flavor rows: ch0..27, (1, -s28/2), (0,0)
__device__ float    g_partial[NTILES];
__device__ float    g_diagpart[NPREP];
__device__ int      g_counter;            // zero-init; reset by last CTA

// ---------------------------------------------------------------------------
// Kernel A (prep): per-point sq (non-FMA tree) + sequential-FMA self-dot ->
// diagonal loss with the reference's rounding-noise structure (bit-identical
// per-point arithmetic to every passing round), plus bf16 packs with the
// norm-augmentation channels (A and B flavors), staged for coalesced stores.
// ---------------------------------------------------------------------------
__global__ __launch_bounds__(64) void prep_kernel(const float* __restrict__ x) {
    __shared__ uint32_t stA[64 * 16];   // 4 KB
    __shared__ uint32_t stB[64 * 16];   // 4 KB
    __shared__ float    red[64];

    int tid = threadIdx.x;
    int n = blockIdx.x * 64 + tid;

    float v[CH];
#pragma unroll
    for (int c = 0; c < CH; ++c) v[c] = x[c * NPTS + n];

    // sq: non-FMA rounded products, 4-accumulator tree (XLA-reduce flavor)
    float a0 = 0.f, a1 = 0.f, a2 = 0.f, a3 = 0.f;
#pragma unroll
    for (int c = 0; c < CH; c += 4) {
        a0 = __fadd_rn(a0, __fmul_rn(v[c + 0], v[c + 0]));
        a1 = __fadd_rn(a1, __fmul_rn(v[c + 1], v[c + 1]));
        a2 = __fadd_rn(a2, __fmul_rn(v[c + 2], v[c + 2]));
        a3 = __fadd_rn(a3, __fmul_rn(v[c + 3], v[c + 3]));
    }
    float sq = __fadd_rn(__fadd_rn(a0, a1), __fadd_rn(a2, a3));
    g_sq[n] = sq;

    // self-dot: sequential FMA chain (GEMM flavor) -> diagonal noise d2 ~ +-eps
    float dot = 0.f;
#pragma unroll
    for (int c = 0; c < CH; ++c) dot = fmaf(v[c], v[c], dot);

    float d2 = fmaf(-2.f, dot, __fadd_rn(sq, sq));
    float f = 0.f;
    if (d2 < 4.f) {
        d2 = fmaxf(d2, 0.f);
        float d = sqrtf(d2);
        f = fmaf(1.5f, d, fmaf(-0.5f, d2, -1.f));
    }

    // 28-channel screen norm (fp32)
    float s28 = 0.f;
#pragma unroll
    for (int c = 0; c < 28; ++c) s28 = fmaf(v[c], v[c], s28);
    float nh = -0.5f * s28;

    // data words 0..13 (channels 0..27), augmentation words 14..15
#pragma unroll
    for (int w = 0; w < 14; ++w) {
        __nv_bfloat162 pk = __floats2bfloat162_rn(v[2 * w], v[2 * w + 1]);
        uint32_t u = *reinterpret_cast<uint32_t*>(&pk);
        stA[tid * 16 + w] = u;
        stB[tid * 16 + w] = u;
    }
    {
        __nv_bfloat162 pa = __floats2bfloat162_rn(nh, 1.0f);   // A: ch28=-s/2, ch29=1
        __nv_bfloat162 pb = __floats2bfloat162_rn(1.0f, nh);   // B: ch28=1, ch29=-s/2
        stA[tid * 16 + 14] = *reinterpret_cast<uint32_t*>(&pa);
        stB[tid * 16 + 14] = *reinterpret_cast<uint32_t*>(&pb);
        stA[tid * 16 + 15] = 0u;                               // ch30, ch31 = 0
        stB[tid * 16 + 15] = 0u;
    }
    __syncthreads();
    uint32_t* dstA = &g_xa[blockIdx.x * 64 * 16];
    uint32_t* dstB = &g_xb[blockIdx.x * 64 * 16];
#pragma unroll
    for (int i = tid; i < 1024; i += 64) {
        dstA[i] = stA[i];
        dstB[i] = stB[i];
    }

    // deterministic block reduction of diagonal contributions
    red[tid] = f;
    __syncthreads();
#pragma unroll
    for (int s = 32; s > 0; s >>= 1) {
        if (tid < s) red[tid] += red[tid + s];
        __syncthreads();
    }
    if (tid == 0) g_diagpart[blockIdx.x] = red[0];
}

// ---------------------------------------------------------------------------
// mma.sync m16n8k16 bf16 (sm_80+ baseline PTX; portable to plain sm_103).
// ---------------------------------------------------------------------------
__device__ __forceinline__ void hmma16816(float* c, const uint32_t* a, const uint32_t* b) {
    asm volatile(
        "mma.sync.aligned.m16n8k16.row.col.f32.bf16.bf16.f32 "
        "{%0,%1,%2,%3}, {%4,%5,%6,%7}, {%8,%9}, {%0,%1,%2,%3};"
        : "+f"(c[0]), "+f"(c[1]), "+f"(c[2]), "+f"(c[3])
        : "r"(a[0]), "r"(a[1]), "r"(a[2]), "r"(a[3]), "r"(b[0]), "r"(b[1]));
}

// ---------------------------------------------------------------------------
// Exact fp32 recompute of one pair (full 32 channels, reference formula).
// Single out-of-line copy shared by all cold paths.
// ---------------------------------------------------------------------------
__device__ __noinline__ float exact_pair(const float* __restrict__ x, int gi, int gj) {
    float dt = 0.f;
#pragma unroll
    for (int c = 0; c < CH; ++c)
        dt = fmaf(x[c * NPTS + gi], x[c * NPTS + gj], dt);
    float e2 = fmaf(-2.f, dt, g_sq[gi] + g_sq[gj]);
    if (e2 < 4.f) {
        e2 = fmaxf(e2, 0.f);
        float d = sqrtf(e2);
        return fmaf(1.5f, d, fmaf(-0.5f, e2, -1.f));
    }
    return 0.f;
}

// ---------------------------------------------------------------------------
// Cold path: lane-exact fp32 recompute of this lane's 8 rows x 32 cols.
// Runs only when the screen flags (P ~ 1e-8 per pair off-diagonal).
// ---------------------------------------------------------------------------
__device__ __noinline__ float slow_lane(const float* __restrict__ x,
                                        int I, int J, int m0, int n0,
                                        int qr, int qc) {
    float acc = 0.f;
#pragma unroll 1
    for (int r = 0; r < 8; ++r) {
        int gi = I * TILE + m0 + (r >> 1) * 16 + qr + (r & 1) * 8;
#pragma unroll 1
        for (int cidx = 0; cidx < 32; ++cidx) {
            int gj = J * TILE + n0 + (cidx >> 1) * 8 + 2 * qc + (cidx & 1);
            if (gi != gj) acc += exact_pair(x, gi, gj);
        }
    }
    return acc;
}

// ---------------------------------------------------------------------------
// Kernel B (tile): one CTA per (I,J) 256x256 tile pair, J >= I, 8 warps.
// K=32 bf16 HMMA with NORM AUGMENTATION: acc = dot28 - s28_i/2 - s28_j/2.
// Screen: d2_full < 4 ==> acc > -3 (sound; errors <= 0.55, margin > 0.4).
// Off-diagonal hot loop per nj: 4 LDS + 8 MMA + 16 FMNMX, nothing else.
// Diagonal tiles: per-element flag -> shared exact_pair (gi==gj skipped;
// diagonal loss handled in prep). Last CTA does the final reduction.
// ---------------------------------------------------------------------------
__global__ __launch_bounds__(256, 4) void tile_kernel(const float* __restrict__ x,
                                                      float* __restrict__ out) {
    __shared__ __align__(16) uint32_t As[TILE * LDPW];   // 20 KB
    __shared__ __align__(16) uint32_t Bs[TILE * LDPW];   // 20 KB
    __shared__ float red[256];
    __shared__ bool  amlast;

    int tid = threadIdx.x;
    int wid = tid >> 5;
    int lane = tid & 31;

    // decode blockIdx -> (I, J) over upper triangle
    int bid = blockIdx.x;
    int I = 0, rem = bid;
    while (rem >= MT - I) { rem -= MT - I; ++I; }
    int J = I + rem;
    bool diag = (I == J);

    // fill A/B tiles: 256 threads, 2 tiles x 256 rows -> 2 rows per thread.
    // A rows from g_xa[I..], B rows from g_xb[J..] (works for diag too).
    {
        int which = tid >> 7;                  // 0 -> A, 1 -> B
        int r0 = tid & 127;
        const uint32_t* gsrc = which ? g_xb : g_xa;
        int tilebase = (which ? J : I) * TILE;
#pragma unroll
        for (int rr = 0; rr < 2; ++rr) {
            int row = r0 + rr * 128;
            const uint4* src = reinterpret_cast<const uint4*>(&gsrc[(tilebase + row) * 16]);
            uint4* dst = reinterpret_cast<uint4*>((which ? Bs : As) + row * LDPW);
#pragma unroll
            for (int q = 0; q < 4; ++q) dst[q] = src[q];
        }
    }
    __syncthreads();

    int m0 = (wid & 3) * 64;     // row block of this warp (64 rows)
    int n0 = (wid >> 2) * 128;   // col block of this warp (128 cols)
    int qr = lane >> 2;          // 0..7
    int qc = lane & 3;           // 0..3

    // A fragments: afr[mi][kf][4], mi = 0..3 (16-row slabs)
    uint32_t afr[4][2][4];
#pragma unroll
    for (int mi = 0; mi < 4; ++mi) {
        int r0 = m0 + mi * 16 + qr;
        int r1 = r0 + 8;
#pragma unroll
        for (int kf = 0; kf < 2; ++kf) {
            int kw = kf * 8 + qc;
            afr[mi][kf][0] = As[r0 * LDPW + kw];
            afr[mi][kf][1] = As[r1 * LDPW + kw];
            afr[mi][kf][2] = As[r0 * LDPW + kw + 4];
            afr[mi][kf][3] = As[r1 * LDPW + kw + 4];
        }
    }

    float local = 0.f;

    if (!diag) {
        // ---- hot path: 16 njs of 8 MMAs + vmax tracking; zero branches ----
        float vmax = -1e30f;
#pragma unroll
        for (int nj = 0; nj < 16; ++nj) {
            int jrow = n0 + nj * 8 + qr;
            uint32_t bfr[2][2];
#pragma unroll
            for (int kf = 0; kf < 2; ++kf) {
                int kw = kf * 8 + qc;
                bfr[kf][0] = Bs[jrow * LDPW + kw];
                bfr[kf][1] = Bs[jrow * LDPW + kw + 4];
            }
            float acc[4][4];
#pragma unroll
            for (int mi = 0; mi < 4; ++mi) {
                acc[mi][0] = acc[mi][1] = acc[mi][2] = acc[mi][3] = 0.f;
                hmma16816(acc[mi], afr[mi][0], bfr[0]);
                hmma16816(acc[mi], afr[mi][1], bfr[1]);
            }
#pragma unroll
            for (int mi = 0; mi < 4; ++mi) {
                vmax = fmaxf(vmax, fmaxf(fmaxf(acc[mi][0], acc[mi][1]),
                                         fmaxf(acc[mi][2], acc[mi][3])));
            }
        }
        float contrib = 0.f;
        if (vmax > -3.f)   // sound screen: d2_full < 4 ==> acc > -3
            contrib = slow_lane(x, I, J, m0, n0, qr, qc);
        local = 2.f * contrib;   // symmetry: (I,J) and (J,I) identical
    } else {
        // ---- diagonal tile: per-element flag -> exact recompute ----
#pragma unroll
        for (int nj = 0; nj < 16; ++nj) {
            int jrow = n0 + nj * 8 + qr;
            uint32_t bfr[2][2];
#pragma unroll
            for (int kf = 0; kf < 2; ++kf) {
                int kw = kf * 8 + qc;
                bfr[kf][0] = Bs[jrow * LDPW + kw];
                bfr[kf][1] = Bs[jrow * LDPW + kw + 4];
            }
            float acc[4][4];
#pragma unroll
            for (int mi = 0; mi < 4; ++mi) {
                acc[mi][0] = acc[mi][1] = acc[mi][2] = acc[mi][3] = 0.f;
                hmma16816(acc[mi], afr[mi][0], bfr[0]);
                hmma16816(acc[mi], afr[mi][1], bfr[1]);
            }
            int colb = n0 + nj * 8 + 2 * qc;
#pragma unroll
            for (int mi = 0; mi < 4; ++mi) {
#pragma unroll
                for (int e = 0; e < 4; ++e) {
                    if (acc[mi][e] > -3.f) {   // flags the exact diagonal + rare
                        int gi = I * TILE + m0 + mi * 16 + qr + (e >> 1) * 8;
                        int gj = J * TILE + colb + (e & 1);
                        if (gi != gj) local += exact_pair(x, gi, gj);
                    }
                }
            }
        }
    }

    // deterministic block reduction
    red[tid] = local;
    __syncthreads();
#pragma unroll
    for (int s = 128; s > 0; s >>= 1) {
        if (tid < s) red[tid] += red[tid + s];
        __syncthreads();
    }
    if (tid == 0) g_partial[bid] = red[0];

    // last CTA performs the deterministic final reduction
    if (tid == 0) {
        __threadfence();
        int prev = atomicAdd(&g_counter, 1);
        amlast = (prev == NTILES - 1);
    }
    __syncthreads();
    if (amlast) {
        float s = 0.f;
        for (int i = tid; i < NTILES; i += 256) s += g_partial[i];
        for (int i = tid; i < NPREP; i += 256) s += g_diagpart[i];
        red[tid] = s;
        __syncthreads();
#pragma unroll
        for (int k = 128; k > 0; k >>= 1) {
            if (tid < k) red[tid] += red[tid + k];
            __syncthreads();
        }
        if (tid == 0) {
            out[0] = 0.25f * red[0];
            g_counter = 0;           // reset for next graph replay
        }
    }
}

// ---------------------------------------------------------------------------
extern "C" void kernel_launch(void* const* d_in, const int* in_sizes, int n_in,
                              void* d_out, int out_size) {
    const float* x = (const float*)d_in[0];   // [1, 32, 8192] fp32, channel-major
    float* out = (float*)d_out;

    prep_kernel<<<NPREP, 64>>>(x);
    tile_kernel<<<NTILES, 256>>>(x, out);
}